// round 8
// baseline (speedup 1.0000x reference)
#include <cuda_runtime.h>
#include <math_constants.h>

#define NN 50000
#define EE 800000
#define CC 128

// ---------------- scratch (static device globals: allocation-free) ----------
__device__ int   g_is64;
__device__ int   g_deg[NN];
__device__ int   g_off[NN + 1];
__device__ int   g_cur[NN];
__device__ int   g_src[EE];
__device__ __align__(16) float g_maxd[(size_t)NN * CC];

// ---------------- dtype detection -------------------------------------------
// int64 little-endian indices < 50000 -> every odd 32-bit word is 0.
// Genuine int32 random indices in [0,50000): 64 consecutive zero odd-words
// is impossible. One thread, ~128 loads.
__global__ void k_detect(const int* __restrict__ ei32) {
    if (threadIdx.x == 0 && blockIdx.x == 0) {
        int acc = 0;
        #pragma unroll 8
        for (int i = 0; i < 64; i++) acc |= ei32[2 * i + 1];
        g_is64 = (acc == 0) ? 1 : 0;
    }
}

__device__ __forceinline__ unsigned load_idx(const void* ei, int pos, int is64) {
    if (is64) return (unsigned)((const long long*)ei)[pos];
    return (unsigned)((const int*)ei)[pos];
}

// ---------------- CSR build -------------------------------------------------
__global__ void k_zero_deg() {
    int i = blockIdx.x * blockDim.x + threadIdx.x;
    if (i < NN) g_deg[i] = 0;
}

__global__ void k_hist(const void* __restrict__ ei) {
    int is64 = g_is64;
    int e = blockIdx.x * blockDim.x + threadIdx.x;
    if (e < EE) {
        unsigned dst = load_idx(ei, EE + e, is64);
        if (dst < NN) atomicAdd(&g_deg[dst], 1);
    }
}

// single-block chunked scan over 50000 ints; zero-padded prefix removes any
// speculative negative shared indexing.
__global__ void k_scan() {
    __shared__ int s[2048];
    __shared__ int carry_s;
    int tid = threadIdx.x;
    if (tid == 0) carry_s = 0;
    s[tid] = 0;                       // pad region [0,1024)
    __syncthreads();
    for (int base = 0; base < NN; base += 1024) {
        int i = base + tid;
        int v = (i < NN) ? g_deg[i] : 0;
        s[1024 + tid] = v;
        __syncthreads();
        #pragma unroll
        for (int o = 1; o < 1024; o <<= 1) {
            int t = s[1024 + tid - o];   // always in-bounds (pad)
            __syncthreads();
            s[1024 + tid] += t;
            __syncthreads();
        }
        int c = carry_s;
        int excl = s[1024 + tid] - v;
        if (i < NN) { g_off[i] = c + excl; g_cur[i] = c + excl; }
        int tot = s[2047];
        __syncthreads();
        if (tid == 0) carry_s = c + tot;
        __syncthreads();
    }
    if (tid == 0) g_off[NN] = carry_s;
}

__global__ void k_scatter(const void* __restrict__ ei) {
    int is64 = g_is64;
    int e = blockIdx.x * blockDim.x + threadIdx.x;
    if (e < EE) {
        unsigned src = load_idx(ei, e, is64);
        unsigned dst = load_idx(ei, EE + e, is64);
        if (src < NN && dst < NN) {
            int p = atomicAdd(&g_cur[dst], 1);
            if (p >= 0 && p < EE) g_src[p] = (int)src;
        }
    }
}

// ---------------- warp-per-node segment max --------------------------------
// Each warp owns one node: lane holds a float4 (4 of the 128 channels).
__global__ void k_nodemax(const float* __restrict__ x) {
    int gw   = (blockIdx.x * blockDim.x + threadIdx.x) >> 5;
    int lane = threadIdx.x & 31;
    if (gw >= NN) return;

    const float4* x4 = (const float4*)x;
    float4 xd = x4[gw * 32 + lane];

    float4 m = make_float4(-CUDART_INF_F, -CUDART_INF_F, -CUDART_INF_F, -CUDART_INF_F);
    int beg = g_off[gw];
    int end = g_off[gw + 1];

    for (int e = beg; e < end; e++) {
        unsigned s = (unsigned)g_src[e];       // uniform across warp -> broadcast
        if (s >= NN) continue;
        float4 xs = x4[s * 32 + lane];
        m.x = fmaxf(m.x, xs.x - xd.x);
        m.y = fmaxf(m.y, xs.y - xd.y);
        m.z = fmaxf(m.z, xs.z - xd.z);
        m.w = fmaxf(m.w, xs.w - xd.w);
    }
    if (beg >= end) m = make_float4(0.f, 0.f, 0.f, 0.f);
    ((float4*)g_maxd)[gw * 32 + lane] = m;
}

// ---------------- fused concat-GEMM: out = x@W_top + maxd@W_bot + b --------
// 128x128 block tile, BK=16, 256 threads, 8x8 register tile per thread.
// Two k-passes (x then g_maxd) — pointer is loop-invariant per pass.
__global__ __launch_bounds__(256) void k_gemm(
    const float* __restrict__ x,
    const float* __restrict__ W,
    const float* __restrict__ b,
    float* __restrict__ out)
{
    __shared__ float As[16][132];   // padded: transpose-store conflict relief
    __shared__ float Bs[16][128];

    int tid  = threadIdx.x;
    int row0 = blockIdx.x * 128;
    int ty = tid / 16, tx = tid % 16;     // 16x16 thread grid
    int ar = tid >> 2, ac = tid & 3;      // A-load: rows {ar, ar+64}, k-chunk ac
    int bkr = tid >> 5, bc = tid & 31;    // B-load: kk rows {bkr, bkr+8}, col chunk bc

    float acc[8][8];
    #pragma unroll
    for (int i = 0; i < 8; i++)
        #pragma unroll
        for (int j = 0; j < 8; j++) acc[i][j] = 0.f;

    #pragma unroll 1
    for (int pass = 0; pass < 2; pass++) {
        const float* Asrc = (pass == 0) ? x : (const float*)g_maxd;
        int kbase = pass * 128;

        #pragma unroll 1
        for (int koff = 0; koff < 128; koff += 16) {
            // A tile (128 rows x 16 k), stored transposed As[kk][row]
            #pragma unroll
            for (int s = 0; s < 2; s++) {
                int r  = ar + s * 64;
                int gr = row0 + r;
                float4 v = make_float4(0.f, 0.f, 0.f, 0.f);
                if (gr < NN)
                    v = *(const float4*)(Asrc + (size_t)gr * 128 + koff + ac * 4);
                As[ac * 4 + 0][r] = v.x;
                As[ac * 4 + 1][r] = v.y;
                As[ac * 4 + 2][r] = v.z;
                As[ac * 4 + 3][r] = v.w;
            }
            // B tile (16 k x 128 cols), natural layout
            #pragma unroll
            for (int s = 0; s < 2; s++) {
                int kk = bkr + s * 8;
                *(float4*)&Bs[kk][bc * 4] =
                    *(const float4*)(W + (size_t)(kbase + koff + kk) * 128 + bc * 4);
            }
            __syncthreads();

            #pragma unroll
            for (int kk = 0; kk < 16; kk++) {
                float a[8], bb[8];
                #pragma unroll
                for (int i = 0; i < 8; i++) a[i] = As[kk][ty * 8 + i];
                #pragma unroll
                for (int j = 0; j < 8; j++) bb[j] = Bs[kk][tx * 8 + j];
                #pragma unroll
                for (int i = 0; i < 8; i++)
                    #pragma unroll
                    for (int j = 0; j < 8; j++)
                        acc[i][j] += a[i] * bb[j];
            }
            __syncthreads();
        }
    }

    float bias[8];
    #pragma unroll
    for (int j = 0; j < 8; j++) bias[j] = b[tx * 8 + j];

    #pragma unroll
    for (int i = 0; i < 8; i++) {
        int gr = row0 + ty * 8 + i;
        if (gr < NN) {
            #pragma unroll
            for (int j = 0; j < 8; j += 4) {
                float4 v;
                v.x = acc[i][j + 0] + bias[j + 0];
                v.y = acc[i][j + 1] + bias[j + 1];
                v.z = acc[i][j + 2] + bias[j + 2];
                v.w = acc[i][j + 3] + bias[j + 3];
                *(float4*)(out + (size_t)gr * 128 + tx * 8 + j) = v;
            }
        }
    }
}

// ---------------- launch ----------------------------------------------------
extern "C" void kernel_launch(void* const* d_in, const int* in_sizes, int n_in,
                              void* d_out, int out_size) {
    // Identify inputs by element count (all four are distinct) — immune to
    // any metadata ordering surprises.
    const float* x  = nullptr;   // 50000*128   = 6400000 f32
    const void*  ei = nullptr;   // 2*800000    = 1600000 elems (int32 OR int64)
    const float* W  = nullptr;   // 256*128     = 32768   f32
    const float* b  = nullptr;   // 128         = 128     f32
    for (int i = 0; i < n_in; i++) {
        switch (in_sizes[i]) {
            case NN * CC:     x  = (const float*)d_in[i]; break;
            case 2 * EE:      ei = d_in[i];               break;
            case 2 * CC * CC: W  = (const float*)d_in[i]; break;
            case CC:          b  = (const float*)d_in[i]; break;
            default: break;
        }
    }
    if (!x)  x  = (const float*)d_in[0];
    if (!ei) ei = d_in[1];
    if (!W)  W  = (const float*)d_in[2];
    if (!b)  b  = (const float*)d_in[3];
    float* out = (float*)d_out;

    k_detect<<<1, 32>>>((const int*)ei);
    k_zero_deg<<<(NN + 255) / 256, 256>>>();
    k_hist<<<EE / 256, 256>>>(ei);
    k_scan<<<1, 1024>>>();
    k_scatter<<<EE / 256, 256>>>(ei);
    k_nodemax<<<(NN + 7) / 8, 256>>>(x);          // 8 warps/block, warp-per-node
    k_gemm<<<(NN + 127) / 128, 256>>>(x, W, b, out);
}